// round 8
// baseline (speedup 1.0000x reference)
#include <cuda_runtime.h>

// QConv1d, conjugation closed form; 4 co per thread as TWO f32x2 co-pairs.
// t scalar per thread; co-invariant rotation ingredients amortized over 4 co.
// x: (B, CIN, T, 4)   a,b,c: (COUT, CIN, FL)   out: (B, COUT, TOUT, 4)

#define B_    2
#define CIN_  16
#define COUT_ 16
#define T_    2048
#define FL_   9
#define TOUT_ 2040
#define NQ    4        // co per thread (2 packed pairs)
#define GRP   8        // ci groups per block; each handles 2 ci

typedef unsigned long long ull;

__device__ __forceinline__ ull pk2(float lo, float hi) {
    ull r; asm("mov.b64 %0,{%1,%2};" : "=l"(r)
               : "r"(__float_as_uint(lo)), "r"(__float_as_uint(hi)));
    return r;
}
__device__ __forceinline__ void upk2(ull v, float& lo, float& hi) {
    unsigned a, b; asm("mov.b64 {%0,%1},%2;" : "=r"(a), "=r"(b) : "l"(v));
    lo = __uint_as_float(a); hi = __uint_as_float(b);
}
__device__ __forceinline__ ull bc2(float v) { return pk2(v, v); }
__device__ __forceinline__ ull f2(ull a, ull b, ull c) {
    ull r; asm("fma.rn.f32x2 %0,%1,%2,%3;" : "=l"(r) : "l"(a), "l"(b), "l"(c));
    return r;
}
__device__ __forceinline__ ull m2(ull a, ull b) {
    ull r; asm("mul.rn.f32x2 %0,%1,%2;" : "=l"(r) : "l"(a), "l"(b));
    return r;
}
__device__ __forceinline__ ull a2_(ull a, ull b) {
    ull r; asm("add.rn.f32x2 %0,%1,%2;" : "=l"(r) : "l"(a), "l"(b));
    return r;
}
__device__ __forceinline__ float rcpf(float x) {
    float r; asm("rcp.approx.f32 %0,%1;" : "=f"(r) : "f"(x));
    return r;
}
__device__ __forceinline__ ull rcp2(ull v) {
    float lo, hi; upk2(v, lo, hi);
    return pk2(rcpf(lo), rcpf(hi));
}

__global__ __launch_bounds__(32 * GRP)
void qconv1d_kernel(const float* __restrict__ x,
                    const float* __restrict__ pa,
                    const float* __restrict__ pb,
                    const float* __restrict__ pc,
                    float* __restrict__ out)
{
    __shared__ ull sp[CIN_][FL_][3][2];          // {a,b,c} x {pair0,pair1}
    __shared__ ull red[GRP - 1][32][2][4];

    const int tx  = threadIdx.x;
    const int g   = threadIdx.y;                 // ci group 0..7
    const int tid = g * 32 + tx;
    const int t   = blockIdx.x * 32 + tx;
    const int co0 = blockIdx.y * NQ;
    const int b   = blockIdx.z;
    const int tL  = t < TOUT_ ? t : (TOUT_ - 1);

    // pack params: 16*9*3*2 = 864 packed entries, 256 threads
    for (int e2 = tid; e2 < CIN_ * FL_ * 3 * 2; e2 += 32 * GRP) {
        const int j   = e2 & 1;
        const int e   = e2 >> 1;
        const int prm = e % 3;
        const int f   = (e / 3) % FL_;
        const int cci = e / (3 * FL_);
        const int s0 = ((co0 + 2 * j) * CIN_ + cci) * FL_ + f;
        const int s1 = s0 + CIN_ * FL_;
        const float* P = (prm == 0) ? pa : (prm == 1) ? pb : pc;
        sp[cci][f][prm][j] = pk2(__ldg(P + s0), __ldg(P + s1));
    }
    __syncthreads();

    // accumulators per pair: positive {w,x,y,z} and negative-product {S,nx,ny,nz}
    ull aw[2], ax[2], ay[2], az[2], Sn[2], nx[2], ny[2], nz[2];
    #pragma unroll
    for (int j = 0; j < 2; ++j) {
        aw[j]=0; ax[j]=0; ay[j]=0; az[j]=0;
        Sn[j]=0; nx[j]=0; ny[j]=0; nz[j]=0;
    }

    #pragma unroll
    for (int cc = 0; cc < 2; ++cc) {
        const int ci = g + cc * GRP;
        const float4* xr = reinterpret_cast<const float4*>(x)
                         + ((size_t)b * CIN_ + ci) * T_ + tL;

        const float4 v4 = __ldg(xr + 4);               // center tap qp
        const float pw = v4.x, vx = v4.y, vy = v4.z, vz = v4.w;
        const float vsq  = vx * vx + vy * vy + vz * vz;
        const float nvsq = -vsq;
        const ull pw2  = bc2(pw);
        const ull vsq2 = bc2(vsq);

        #pragma unroll
        for (int f = 0; f < FL_; ++f) {
            const float4 u4 = __ldg(xr + f);
            const float s = u4.x, ux = u4.y, uy = u4.z, uz = u4.w;

            // scalar co-invariants: R(w) = w^2 u + w (2 v x u) + (2d v - vsq u)
            const float d  = vx*ux + vy*uy + vz*uz;
            const float dd = d + d;
            float crx = vy*uz - vz*uy;  crx += crx;
            float cry = vz*ux - vx*uz;  cry += cry;
            float crz = vx*uy - vy*ux;  crz += crz;
            const float a0x = fmaf(dd, vx, nvsq * ux);
            const float a0y = fmaf(dd, vy, nvsq * uy);
            const float a0z = fmaf(dd, vz, nvsq * uz);

            // broadcast once per f, shared by both co-pairs
            const ull s2   = bc2(s);
            const ull ux2  = bc2(ux);
            const ull uy2  = bc2(uy);
            const ull uz2  = bc2(uz);
            const ull crx2 = bc2(crx);
            const ull cry2 = bc2(cry);
            const ull crz2 = bc2(crz);
            const ull a0x2 = bc2(a0x);
            const ull a0y2 = bc2(a0y);
            const ull a0z2 = bc2(a0z);

            #pragma unroll
            for (int j = 0; j < 2; ++j) {
                const ull A2 = sp[ci][f][0][j];
                const ull B2 = sp[ci][f][1][j];
                const ull C2 = sp[ci][f][2][j];

                const ull w2   = a2_(pw2, C2);
                const ull nsq2 = f2(w2, w2, vsq2);
                const ull rn2  = rcp2(nsq2);
                const ull arn2 = m2(A2, rn2);

                const ull Rx = m2(f2(w2, f2(w2, ux2, crx2), a0x2), arn2);
                const ull Ry = m2(f2(w2, f2(w2, uy2, cry2), a0y2), arn2);
                const ull Rz = m2(f2(w2, f2(w2, uz2, crz2), a0z2), arn2);
                const ull Rw = m2(s2, A2);
                const ull qw2 = a2_(s2, B2);

                // positive parts
                aw[j] = f2(qw2, Rw, aw[j]);
                ax[j] = f2(qw2, Rx, ax[j]);
                ax[j] = f2(ux2, Rw, ax[j]);
                ax[j] = f2(uy2, Rz, ax[j]);
                ay[j] = f2(qw2, Ry, ay[j]);
                ay[j] = f2(uy2, Rw, ay[j]);
                ay[j] = f2(uz2, Rx, ay[j]);
                az[j] = f2(qw2, Rz, az[j]);
                az[j] = f2(uz2, Rw, az[j]);
                az[j] = f2(ux2, Ry, az[j]);
                // negative parts (subtracted once at the end)
                Sn[j] = f2(ux2, Rx, Sn[j]);
                Sn[j] = f2(uy2, Ry, Sn[j]);
                Sn[j] = f2(uz2, Rz, Sn[j]);
                nx[j] = f2(uz2, Ry, nx[j]);
                ny[j] = f2(ux2, Rz, ny[j]);
                nz[j] = f2(uy2, Rx, nz[j]);
            }
        }
    }

    // fold negatives:  acc = pos - neg
    const ull NEG1 = bc2(-1.0f);
    #pragma unroll
    for (int j = 0; j < 2; ++j) {
        aw[j] = f2(Sn[j], NEG1, aw[j]);
        ax[j] = f2(nx[j], NEG1, ax[j]);
        ay[j] = f2(ny[j], NEG1, ay[j]);
        az[j] = f2(nz[j], NEG1, az[j]);
    }

    // flat reduction over the 8 ci groups
    if (g > 0) {
        #pragma unroll
        for (int j = 0; j < 2; ++j) {
            red[g - 1][tx][j][0] = aw[j];
            red[g - 1][tx][j][1] = ax[j];
            red[g - 1][tx][j][2] = ay[j];
            red[g - 1][tx][j][3] = az[j];
        }
    }
    __syncthreads();
    if (g == 0 && t < TOUT_) {
        #pragma unroll
        for (int j = 0; j < 2; ++j) {
            ull w = aw[j], X = ax[j], Y = ay[j], Z = az[j];
            #pragma unroll
            for (int k = 0; k < GRP - 1; ++k) {
                w = a2_(w, red[k][tx][j][0]);
                X = a2_(X, red[k][tx][j][1]);
                Y = a2_(Y, red[k][tx][j][2]);
                Z = a2_(Z, red[k][tx][j][3]);
            }
            float w0, w1, x0, x1, y0, y1, z0, z1;
            upk2(w, w0, w1); upk2(X, x0, x1); upk2(Y, y0, y1); upk2(Z, z0, z1);
            float4* o4 = reinterpret_cast<float4*>(out)
                       + (size_t)b * COUT_ * TOUT_ + t;
            o4[(size_t)(co0 + 2*j + 0) * TOUT_] = make_float4(w0, x0, y0, z0);
            o4[(size_t)(co0 + 2*j + 1) * TOUT_] = make_float4(w1, x1, y1, z1);
        }
    }
}

extern "C" void kernel_launch(void* const* d_in, const int* in_sizes, int n_in,
                              void* d_out, int out_size)
{
    const float* x  = (const float*)d_in[0];
    const float* pa = (const float*)d_in[1];
    const float* pb = (const float*)d_in[2];
    const float* pc = (const float*)d_in[3];
    float* out = (float*)d_out;

    dim3 block(32, GRP, 1);
    dim3 grid((TOUT_ + 31) / 32, COUT_ / NQ, B_);
    qconv1d_kernel<<<grid, block>>>(x, pa, pb, pc, out);
}